// round 10
// baseline (speedup 1.0000x reference)
#include <cuda_runtime.h>
#include <math_constants.h>

// Roi_61564061221098 round 10: NHWC restructure.
//  transpose: x (NCHW) -> g_nhwc [n][h][w][c]; position stride 2048B aligned.
//  roi_prep:  packed absolute bin geometry per roi (XLA-exact: x/7 as x*fl(1/7)).
//  roi_pool:  block = roi, warp = 64 contiguous channels (lane = 2 ch, float2).
//             Bins are warp-uniform -> accumulate each (ph,pw) bin in registers
//             straight from LDG.64 (one instr = 64 channels, 2 wavefronts).
//             Outputs staged in smem [bin][514] then flushed coalesced.

#define NC    512
#define FH    50
#define FW    68
#define NPOS  (FH * FW)          // 3400
#define PP    7
#define SCALE 0.0625f
#define NEG_INF (-CUDART_INF_F)
#define SB_STRIDE 514            // bin row stride (even: 8B-aligned float2; 2-way max)
#define SB_FLOATS (49 * SB_STRIDE)

__device__ float g_nhwc[4 * NPOS * NC];     // 27.85 MB scratch
// per-roi record: [0]=image n, [3..9] = hs | he<<8 | ws<<16 | we<<24 (absolute)
__device__ __align__(16) int g_rec[4096 * 16];

__global__ void transpose_kernel(const float* __restrict__ x)
{
    __shared__ float tile[32][33];
    const int n  = blockIdx.z;
    const int c0 = blockIdx.y * 32;
    const int p0 = blockIdx.x * 32;
    const int tx = threadIdx.x, ty = threadIdx.y;    // block (32, 8)

#pragma unroll
    for (int dy = 0; dy < 32; dy += 8) {
        const int c = c0 + ty + dy;
        const int p = p0 + tx;
        tile[ty + dy][tx] = (p < NPOS) ? x[(n * NC + c) * NPOS + p] : 0.0f;
    }
    __syncthreads();
#pragma unroll
    for (int dy = 0; dy < 32; dy += 8) {
        const int p = p0 + ty + dy;
        if (p < NPOS) g_nhwc[((size_t)n * NPOS + p) * NC + c0 + tx] = tile[tx][ty + dy];
    }
}

__global__ void roi_prep(const float* __restrict__ rois,
                         const int*   __restrict__ ridx, int R)
{
    int r = blockIdx.x * blockDim.x + threadIdx.x;
    if (r >= R) return;

    const float y1 = rois[r * 4 + 0];
    const float x1 = rois[r * 4 + 1];
    const float y2 = rois[r * 4 + 2];
    const float x2 = rois[r * 4 + 3];
    const float rb0 = rintf(__fmul_rn(x1, SCALE));
    const float rb1 = rintf(__fmul_rn(y1, SCALE));
    const float rb2 = rintf(__fmul_rn(x2, SCALE));
    const float rb3 = rintf(__fmul_rn(y2, SCALE));
    const float roiw = fmaxf(__fadd_rn(__fsub_rn(rb2, rb0), 1.0f), 1.0f);
    const float roih = fmaxf(__fadd_rn(__fsub_rn(rb3, rb1), 1.0f), 1.0f);
    const float R7 = (float)(1.0 / 7.0);          // XLA: x/7 -> x * fl(1/7)
    const float bw = __fmul_rn(roiw, R7);
    const float bh = __fmul_rn(roih, R7);

    int* rec = g_rec + r * 16;
    rec[0] = ridx[r];
#pragma unroll
    for (int p = 0; p < PP; p++) {
        const float fp  = (float)p;
        const float fp1 = (float)(p + 1);
        int hs = (int)fminf(fmaxf(__fadd_rn(floorf(__fmul_rn(fp,  bh)), rb1), 0.0f), (float)FH);
        int he = (int)fminf(fmaxf(__fadd_rn(ceilf (__fmul_rn(fp1, bh)), rb1), 0.0f), (float)FH);
        int ws = (int)fminf(fmaxf(__fadd_rn(floorf(__fmul_rn(fp,  bw)), rb0), 0.0f), (float)FW);
        int we = (int)fminf(fmaxf(__fadd_rn(ceilf (__fmul_rn(fp1, bw)), rb0), 0.0f), (float)FW);
        rec[3 + p] = hs | (he << 8) | (ws << 16) | (we << 24);
    }
}

__device__ __forceinline__ void fmax2(float2& a, const float2 b)
{
    a.x = fmaxf(a.x, b.x); a.y = fmaxf(a.y, b.y);
}

__global__ __launch_bounds__(256)
void roi_pool(float* __restrict__ out, int R)
{
    extern __shared__ float sbin[];                 // [49][SB_STRIDE]

    const int r    = blockIdx.x;
    const int warp = threadIdx.x >> 5;
    const int lane = threadIdx.x & 31;
    const int c0   = warp * 64 + lane * 2;          // 8 warps * 64 ch = 512

    int v = 0;
    if (lane < 16) v = g_rec[r * 16 + lane];
    const int n = __shfl_sync(0xffffffffu, v, 0);

    // float2 view: position stride = NC/2 = 256 float2
    const float2* __restrict__ base =
        (const float2*)g_nhwc + ((size_t)n * NPOS * NC + c0) / 2;

#pragma unroll
    for (int ph = 0; ph < PP; ph++) {
        const int pk = __shfl_sync(0xffffffffu, v, 3 + ph);
        const int h0 = pk & 0xff;
        const int h1 = (pk >> 8) & 0xff;

        for (int pw = 0; pw < PP; pw++) {
            const int qk = __shfl_sync(0xffffffffu, v, 3 + pw);
            const int w0 = (qk >> 16) & 0xff;
            const int w1 = (qk >> 24) & 0xff;

            float2 m0 = make_float2(NEG_INF, NEG_INF);
            float2 m1 = m0;
            for (int h = h0; h < h1; h++) {
                const float2* p = base + (h * FW + w0) * (NC / 2);
                int w = w0;
                for (; w + 2 <= w1; w += 2, p += NC) {   // 2x unroll for MLP
                    fmax2(m0, p[0]);
                    fmax2(m1, p[NC / 2]);
                }
                if (w < w1) fmax2(m0, p[0]);
            }
            fmax2(m0, m1);
            // empty bin -> 0.0 per reference isfinite rule
            float2 o = make_float2(m0.x == NEG_INF ? 0.0f : m0.x,
                                   m0.y == NEG_INF ? 0.0f : m0.y);
            *(float2*)&sbin[(ph * PP + pw) * SB_STRIDE + c0] = o;
        }
    }
    __syncthreads();

    // coalesced flush: out[r][ch][bin], 25088 floats
    const size_t ob = (size_t)r * (NC * 49);
    for (int i = threadIdx.x; i < NC * 49; i += 256) {
        const int ch  = i / 49;
        const int bin = i - ch * 49;
        out[ob + i] = sbin[bin * SB_STRIDE + ch];
    }
}

extern "C" void kernel_launch(void* const* d_in, const int* in_sizes, int n_in,
                              void* d_out, int out_size)
{
    const float* x    = (const float*)d_in[0];
    const float* rois = (const float*)d_in[1];
    const int*   ridx = (const int*)d_in[2];
    float*       out  = (float*)d_out;
    const int R = in_sizes[2];

    static int smem_set = 0;
    if (!smem_set) {
        cudaFuncSetAttribute(roi_pool, cudaFuncAttributeMaxDynamicSharedMemorySize,
                             SB_FLOATS * 4);
        smem_set = 1;
    }

    dim3 tgrid((NPOS + 31) / 32, NC / 32, 4);
    transpose_kernel<<<tgrid, dim3(32, 8)>>>(x);
    roi_prep<<<(R + 255) / 256, 256>>>(rois, ridx, R);
    roi_pool<<<R, 256, SB_FLOATS * 4>>>(out, R);
}

// round 11
// speedup vs baseline: 1.2700x; 1.2700x over previous
#include <cuda_runtime.h>
#include <math_constants.h>

// Roi_61564061221098 round 11: smem-staged column sweep.
// Block = (image, 4 contiguous channels, roi-half): 4*128*2 = 1024 blocks,
// 74.2KB smem -> 3 blocks/SM (one wave-ish). Each block stages its 4 planes
// once (global reads = input size), then warps pool rois from shared memory:
//   sweep:  lane = ch(0-3)*8 + colgroup(0-7); LDS.128 = 32 cols x 4 ch / instr
//   reduce: lane = ch(0-3)*8 + pw(0-6); per-pw segmented max over col buffer
// Bin geometry (XLA-exact: x/7 as x*fl(1/7)) precomputed by roi_prep.

#define NC    512
#define FH    50
#define FW    68
#define NPOS  (FH * FW)
#define PP    7
#define SCALE 0.0625f
#define NEG_INF (-CUDART_INF_F)
#define MAXR  2048
#define PSTR  3404          // smem plane stride (floats): 16B-mult, covers overread
#define CBSTR 104           // column buffer stride per channel (floats)
#define SMEMF (4 * PSTR + 8 * 4 * CBSTR + 8 * 200)   // 18544 floats = 74176 B

// per-roi record: [0]=w0a, [1]=span(=we6-w0a), [2]=maxw,
// [3..9] = hs | he<<8 | (ws-w0a)<<16 | (we-w0a)<<24
__device__ __align__(16) int g_rec[4096 * 16];
__device__ int g_list[4 * MAXR];
__device__ int g_cnt[4];

__global__ void roi_prep(const float* __restrict__ rois,
                         const int*   __restrict__ ridx, int R)
{
    const int tid = threadIdx.x;
    if (tid < 4) g_cnt[tid] = 0;
    __syncthreads();

    for (int r = tid; r < R; r += blockDim.x) {
        const float y1 = rois[r * 4 + 0];
        const float x1 = rois[r * 4 + 1];
        const float y2 = rois[r * 4 + 2];
        const float x2 = rois[r * 4 + 3];
        const float rb0 = rintf(__fmul_rn(x1, SCALE));
        const float rb1 = rintf(__fmul_rn(y1, SCALE));
        const float rb2 = rintf(__fmul_rn(x2, SCALE));
        const float rb3 = rintf(__fmul_rn(y2, SCALE));
        const float roiw = fmaxf(__fadd_rn(__fsub_rn(rb2, rb0), 1.0f), 1.0f);
        const float roih = fmaxf(__fadd_rn(__fsub_rn(rb3, rb1), 1.0f), 1.0f);
        const float R7 = (float)(1.0 / 7.0);      // XLA: x/7 -> x * fl(1/7)
        const float bw = __fmul_rn(roiw, R7);
        const float bh = __fmul_rn(roih, R7);

        const int w0  = (int)fminf(fmaxf(rb0, 0.0f), (float)FW);  // == ws[0]
        const int w0a = w0 & ~3;                                  // 16B-align base
        int maxw = 0;
        int pack[PP];
#pragma unroll
        for (int p = 0; p < PP; p++) {
            const float fp  = (float)p;
            const float fp1 = (float)(p + 1);
            int hs = (int)fminf(fmaxf(__fadd_rn(floorf(__fmul_rn(fp,  bh)), rb1), 0.0f), (float)FH);
            int he = (int)fminf(fmaxf(__fadd_rn(ceilf (__fmul_rn(fp1, bh)), rb1), 0.0f), (float)FH);
            int ws = (int)fminf(fmaxf(__fadd_rn(floorf(__fmul_rn(fp,  bw)), rb0), 0.0f), (float)FW);
            int we = (int)fminf(fmaxf(__fadd_rn(ceilf (__fmul_rn(fp1, bw)), rb0), 0.0f), (float)FW);
            maxw = max(maxw, we - ws);
            pack[p] = hs | (he << 8) | ((ws - w0a) << 16) | ((we - w0a) << 24);
        }
        int* rec = g_rec + r * 16;
        rec[0] = w0a;
        rec[1] = (pack[PP - 1] >> 24) & 0xff;     // span (<= 71)
        rec[2] = maxw;
#pragma unroll
        for (int p = 0; p < PP; p++) rec[3 + p] = pack[p];

        const int n = ridx[r];
        const int pos = atomicAdd(&g_cnt[n], 1);
        if (pos < MAXR) g_list[n * MAXR + pos] = r;
    }
}

__device__ __forceinline__ void fmax4(float4& a, const float4 b)
{
    a.x = fmaxf(a.x, b.x); a.y = fmaxf(a.y, b.y);
    a.z = fmaxf(a.z, b.z); a.w = fmaxf(a.w, b.w);
}

template <int NIT>
__device__ __forceinline__ void pool_roi(const float* __restrict__ sp,
                                         float* __restrict__ cb,
                                         float* __restrict__ so,
                                         int v, int lane)
{
    const int w0a  = __shfl_sync(0xffffffffu, v, 0);
    const int span = __shfl_sync(0xffffffffu, v, 1);
    const int maxw = __shfl_sync(0xffffffffu, v, 2);
    const int ch = lane >> 3;          // 0-3 (both phases)
    const int cg = lane & 7;           // sweep colgroup (4 cols each)
    const int pw = lane & 7;           // reduce pw bin (7 used)
    const int pk0 = __shfl_sync(0xffffffffu, v, 3 + (pw < PP ? pw : 0));
    const int j0 = (pk0 >> 16) & 0xff;
    const int j1 = (pk0 >> 24) & 0xff;

    const float* bp = sp + ch * PSTR + w0a + cg * 4;
    bool act[NIT];
#pragma unroll
    for (int q = 0; q < NIT; q++) act[q] = (q * 32 + cg * 4) < span;

#pragma unroll
    for (int ph = 0; ph < PP; ph++) {
        const int pk = __shfl_sync(0xffffffffu, v, 3 + ph);
        const int h0 = pk & 0xff;
        const int h1 = (pk >> 8) & 0xff;

        float4 m[NIT];
#pragma unroll
        for (int q = 0; q < NIT; q++)
            m[q] = make_float4(NEG_INF, NEG_INF, NEG_INF, NEG_INF);

        const float* p = bp + h0 * FW;
        for (int h = h0; h < h1; h++, p += FW) {
#pragma unroll
            for (int q = 0; q < NIT; q++)
                if (act[q]) fmax4(m[q], *(const float4*)(p + q * 32));
        }

        // column maxes -> buffer [ch][col]
#pragma unroll
        for (int q = 0; q < NIT; q++)
            *(float4*)(cb + ch * CBSTR + q * 32 + cg * 4) = m[q];
        __syncwarp();

        // per-pw segmented max, 4 channels in parallel
        float mm = NEG_INF;
        const float* s = cb + ch * CBSTR;
        for (int k = 0; k < maxw; k++) {
            const int j = j0 + k;
            if (j < j1) mm = fmaxf(mm, s[j]);
        }
        if (pw < PP)
            so[ch * 49 + ph * PP + pw] = (mm == NEG_INF) ? 0.0f : mm;
        __syncwarp();
    }
}

__global__ __launch_bounds__(256, 3)
void roi_pool(const float* __restrict__ x, float* __restrict__ out, int R)
{
    extern __shared__ float smem[];
    float* plane = smem;                                   // [4][PSTR]
    float* cbs   = smem + 4 * PSTR;                        // [8 warps][4*CBSTR]
    float* souts = cbs + 8 * 4 * CBSTR;                    // [8 warps][200]

    const int bid  = blockIdx.x;                           // 4 img * 128 cg * 2
    const int n    = bid >> 8;
    const int rem  = bid & 255;
    const int cgid = rem >> 1;
    const int half = rem & 1;
    const int c0   = cgid * 4;

    const int tid  = threadIdx.x;
    const int warp = tid >> 5;
    const int lane = tid & 31;

    // stage 4 planes: fully coalesced float4 copy (13600 floats)
    {
        const float4* __restrict__ src =
            (const float4*)(x + (size_t)(n * NC + c0) * NPOS);
        for (int i = tid; i < 4 * (NPOS / 4); i += 256) {
            const int ch = i / (NPOS / 4);
            const int p4 = i - ch * (NPOS / 4);
            *(float4*)&plane[ch * PSTR + p4 * 4] = src[i];
        }
    }
    __syncthreads();

    const int cnt = g_cnt[n];
    const int* __restrict__ lst = g_list + n * MAXR;
    float* cb = cbs + warp * (4 * CBSTR);
    float* so = souts + warp * 200;

    for (int ii = half * 8 + warp; ii < cnt; ii += 16) {
        const int r = lst[ii];
        int v = 0;
        if (lane < 16) v = g_rec[r * 16 + lane];
        const int span = __shfl_sync(0xffffffffu, v, 1);

        if (span <= 32)      pool_roi<1>(plane, cb, so, v, lane);
        else if (span <= 64) pool_roi<2>(plane, cb, so, v, lane);
        else                 pool_roi<3>(plane, cb, so, v, lane);

        // 196 contiguous floats: out[r][c0..c0+3][49]
        const size_t ob = (size_t)r * (NC * 49) + (size_t)c0 * 49;
#pragma unroll
        for (int i = 0; i < 7; i++) {
            const int idx = i * 32 + lane;
            if (idx < 196) out[ob + idx] = so[idx];
        }
        __syncwarp();
    }
}

extern "C" void kernel_launch(void* const* d_in, const int* in_sizes, int n_in,
                              void* d_out, int out_size)
{
    const float* x    = (const float*)d_in[0];
    const float* rois = (const float*)d_in[1];
    const int*   ridx = (const int*)d_in[2];
    float*       out  = (float*)d_out;
    const int R = in_sizes[2];

    cudaFuncSetAttribute(roi_pool, cudaFuncAttributeMaxDynamicSharedMemorySize,
                         SMEMF * 4);

    roi_prep<<<1, 256>>>(rois, ridx, R);
    roi_pool<<<1024, 256, SMEMF * 4>>>(x, out, R);
}

// round 12
// speedup vs baseline: 1.9118x; 1.5053x over previous
#include <cuda_runtime.h>
#include <math_constants.h>

// Roi_61564061221098 round 12: NHWC, occupancy/ILP-fixed.
//  transpose: x (NCHW) -> g_nhwc4 [n][h][w][c] (position stride 2048B).
//  roi_prep:  packed absolute bin geometry (XLA-exact: x/7 as x*fl(1/7)).
//  roi_pool:  block = (roi, ph-half). 8 warps = 4 ch-slices (128 ch, float4)
//             x 2 pw-groups (pw 0-3 / 4-6). Per bin: batched LDG.128 sweeps,
//             acc in registers -> sbin [bin][517] -> contiguous flush.
//             58KB smem -> 3 blocks/SM (24 warps) for L2-latency cover.

#define NC    512
#define FH    50
#define FW    68
#define NPOS  (FH * FW)          // 3400
#define PP    7
#define SCALE 0.0625f
#define NEG_INF (-CUDART_INF_F)
#define SSTR  517                // sbin row stride (coprime with 32 banks)
#define NB0   28                 // bins in half 0 (ph 0..3)
#define NB1   21                 // bins in half 1 (ph 4..6)
#define SMEMB (NB0 * SSTR * 4)   // 57,904 B

__device__ float4 g_nhwc4[4 * NPOS * (NC / 4)];   // 27.85 MB scratch
// per-roi record: [0]=image n, [3..9] = hs | he<<8 | ws<<16 | we<<24 (absolute)
__device__ __align__(16) int g_rec[4096 * 16];

__global__ void transpose_kernel(const float* __restrict__ x)
{
    __shared__ float tile[32][33];
    const int n  = blockIdx.z;
    const int c0 = blockIdx.y * 32;
    const int p0 = blockIdx.x * 32;
    const int tx = threadIdx.x, ty = threadIdx.y;    // block (32, 8)
    float* __restrict__ dst = (float*)g_nhwc4;

#pragma unroll
    for (int dy = 0; dy < 32; dy += 8) {
        const int c = c0 + ty + dy;
        const int p = p0 + tx;
        tile[ty + dy][tx] = (p < NPOS) ? x[(n * NC + c) * NPOS + p] : 0.0f;
    }
    __syncthreads();
#pragma unroll
    for (int dy = 0; dy < 32; dy += 8) {
        const int p = p0 + ty + dy;
        if (p < NPOS) dst[((size_t)n * NPOS + p) * NC + c0 + tx] = tile[tx][ty + dy];
    }
}

__global__ void roi_prep(const float* __restrict__ rois,
                         const int*   __restrict__ ridx, int R)
{
    int r = blockIdx.x * blockDim.x + threadIdx.x;
    if (r >= R) return;

    const float y1 = rois[r * 4 + 0];
    const float x1 = rois[r * 4 + 1];
    const float y2 = rois[r * 4 + 2];
    const float x2 = rois[r * 4 + 3];
    const float rb0 = rintf(__fmul_rn(x1, SCALE));
    const float rb1 = rintf(__fmul_rn(y1, SCALE));
    const float rb2 = rintf(__fmul_rn(x2, SCALE));
    const float rb3 = rintf(__fmul_rn(y2, SCALE));
    const float roiw = fmaxf(__fadd_rn(__fsub_rn(rb2, rb0), 1.0f), 1.0f);
    const float roih = fmaxf(__fadd_rn(__fsub_rn(rb3, rb1), 1.0f), 1.0f);
    const float R7 = (float)(1.0 / 7.0);          // XLA: x/7 -> x * fl(1/7)
    const float bw = __fmul_rn(roiw, R7);
    const float bh = __fmul_rn(roih, R7);

    int* rec = g_rec + r * 16;
    rec[0] = ridx[r];
#pragma unroll
    for (int p = 0; p < PP; p++) {
        const float fp  = (float)p;
        const float fp1 = (float)(p + 1);
        int hs = (int)fminf(fmaxf(__fadd_rn(floorf(__fmul_rn(fp,  bh)), rb1), 0.0f), (float)FH);
        int he = (int)fminf(fmaxf(__fadd_rn(ceilf (__fmul_rn(fp1, bh)), rb1), 0.0f), (float)FH);
        int ws = (int)fminf(fmaxf(__fadd_rn(floorf(__fmul_rn(fp,  bw)), rb0), 0.0f), (float)FW);
        int we = (int)fminf(fmaxf(__fadd_rn(ceilf (__fmul_rn(fp1, bw)), rb0), 0.0f), (float)FW);
        rec[3 + p] = hs | (he << 8) | (ws << 16) | (we << 24);
    }
}

__device__ __forceinline__ void fmax4(float4& a, const float4 b)
{
    a.x = fmaxf(a.x, b.x); a.y = fmaxf(a.y, b.y);
    a.z = fmaxf(a.z, b.z); a.w = fmaxf(a.w, b.w);
}

__global__ __launch_bounds__(256, 3)
void roi_pool(float* __restrict__ out, int R)
{
    extern __shared__ float sbin[];                 // [nb][SSTR]

    const int bid  = blockIdx.x;
    const int r    = bid >> 1;
    const int half = bid & 1;
    const int tid  = threadIdx.x;
    const int warp = tid >> 5;
    const int lane = tid & 31;
    const int chid = warp & 3;          // 128-channel slice
    const int pwg  = warp >> 2;         // 0: pw 0-3, 1: pw 4-6

    int v = 0;
    if (lane < 16) v = g_rec[r * 16 + lane];
    const int n = __shfl_sync(0xffffffffu, v, 0);

    // float4 lane base: channel chid*128 + lane*4; position stride = 128 float4
    const float4* __restrict__ base =
        g_nhwc4 + (size_t)n * NPOS * (NC / 4) + chid * 32 + lane;

    const int phN = half ? 3 : 4;
    const int ph0 = half ? 4 : 0;
    const int npw = pwg ? 3 : 4;
    const int pw0 = pwg * 4;

    for (int phi = 0; phi < phN; phi++) {
        const int pk = __shfl_sync(0xffffffffu, v, 3 + ph0 + phi);
        const int h0 = pk & 0xff;
        const int h1 = (pk >> 8) & 0xff;

        for (int pwi = 0; pwi < npw; pwi++) {
            const int pw = pw0 + pwi;
            const int qk = __shfl_sync(0xffffffffu, v, 3 + pw);
            const int ws = (qk >> 16) & 0xff;
            const int we = (qk >> 24) & 0xff;
            const int cnt = we - ws;

            float4 m0 = make_float4(NEG_INF, NEG_INF, NEG_INF, NEG_INF);
            float4 m1 = m0, m2 = m0, m3 = m0;

            for (int h = h0; h < h1; h++) {
                const float4* p = base + (h * FW + ws) * (NC / 4);
                int w = 0;
                for (; w + 4 <= cnt; w += 4) {         // batched loads -> MLP 4
                    const float4 v0 = p[(w + 0) * (NC / 4)];
                    const float4 v1 = p[(w + 1) * (NC / 4)];
                    const float4 v2 = p[(w + 2) * (NC / 4)];
                    const float4 v3 = p[(w + 3) * (NC / 4)];
                    fmax4(m0, v0); fmax4(m1, v1); fmax4(m2, v2); fmax4(m3, v3);
                }
                if (w     < cnt) fmax4(m0, p[(w + 0) * (NC / 4)]);
                if (w + 1 < cnt) fmax4(m1, p[(w + 1) * (NC / 4)]);
                if (w + 2 < cnt) fmax4(m2, p[(w + 2) * (NC / 4)]);
            }
            fmax4(m0, m1); fmax4(m2, m3); fmax4(m0, m2);

            // empty bin -> 0.0 per reference isfinite rule
            const int b = phi * PP + pw;               // local bin index
            float* s = sbin + b * SSTR + chid * 128 + lane * 4;
            s[0] = (m0.x == NEG_INF) ? 0.0f : m0.x;
            s[1] = (m0.y == NEG_INF) ? 0.0f : m0.y;
            s[2] = (m0.z == NEG_INF) ? 0.0f : m0.z;
            s[3] = (m0.w == NEG_INF) ? 0.0f : m0.w;
        }
    }
    __syncthreads();

    // contiguous-ish flush: out[r][ch][half ? 28+b : b]
    const size_t ob = (size_t)r * (NC * 49) + (half ? NB0 : 0);
    if (half == 0) {
        for (int i = tid; i < NB0 * NC; i += 256) {
            const int ch = i / NB0;
            const int b  = i - ch * NB0;
            out[ob + ch * 49 + b] = sbin[b * SSTR + ch];
        }
    } else {
        for (int i = tid; i < NB1 * NC; i += 256) {
            const int ch = i / NB1;
            const int b  = i - ch * NB1;
            out[ob + ch * 49 + b] = sbin[b * SSTR + ch];
        }
    }
}

extern "C" void kernel_launch(void* const* d_in, const int* in_sizes, int n_in,
                              void* d_out, int out_size)
{
    const float* x    = (const float*)d_in[0];
    const float* rois = (const float*)d_in[1];
    const int*   ridx = (const int*)d_in[2];
    float*       out  = (float*)d_out;
    const int R = in_sizes[2];

    cudaFuncSetAttribute(roi_pool, cudaFuncAttributeMaxDynamicSharedMemorySize,
                         SMEMB);

    dim3 tgrid((NPOS + 31) / 32, NC / 32, 4);
    transpose_kernel<<<tgrid, dim3(32, 8)>>>(x);
    roi_prep<<<(R + 255) / 256, 256>>>(rois, ridx, R);
    roi_pool<<<R * 2, 256, SMEMB>>>(out, R);
}